// round 6
// baseline (speedup 1.0000x reference)
#include <cuda_runtime.h>
#include <cstdint>

// Problem constants (fixed by reference setup_inputs)
#define BATCH 2
#define HH 48
#define WW 48
#define CC 512
#define NH 8
#define HD 64
#define KK 7
#define NPIX (BATCH*HH*WW)          // 4608
#define QKV_M (3*CC)                 // 1536

// Scratch (static device globals; 16B-aligned for vector access)
__device__ __align__(16) float g_qkv[(size_t)NPIX * QKV_M];   // 28.3 MB
__device__ __align__(16) float g_att[(size_t)NPIX * CC];      // 9.4 MB (tf32-rounded)
__device__ __align__(16) float g_x  [(size_t)NPIX * CC];      // 9.4 MB (tf32-rounded x)
__device__ __align__(16) float g_w1 [(size_t)QKV_M * CC];     // 3.0 MB (tf32 qkv_w)
__device__ __align__(16) float g_w2 [(size_t)CC * CC];        // 1.0 MB (tf32 proj_w)

// ---------------------------------------------------------------------------
// helpers
// ---------------------------------------------------------------------------
__device__ __forceinline__ uint32_t smem_u32(const void* p) {
    uint32_t a;
    asm("{ .reg .u64 t; cvta.to.shared.u64 t, %1; cvt.u32.u64 %0, t; }" : "=r"(a) : "l"(p));
    return a;
}
__device__ __forceinline__ uint32_t f2tf32(float x) {
    uint32_t r; asm("cvt.rna.tf32.f32 %0, %1;" : "=r"(r) : "f"(x)); return r;
}
__device__ __forceinline__ float f2tf32f(float x) {
    return __uint_as_float(f2tf32(x));
}
#define CP16(dst, src)  asm volatile("cp.async.cg.shared.global [%0], [%1], 16;" :: "r"(dst), "l"(src) : "memory")
#define CP_COMMIT()     asm volatile("cp.async.commit_group;" ::: "memory")
#define CP_WAIT(n)      asm volatile("cp.async.wait_group %0;" :: "n"(n) : "memory")

#define MMA_TF32(c, a, b) \
    asm volatile("mma.sync.aligned.m16n8k8.row.col.f32.tf32.tf32.f32 " \
        "{%0,%1,%2,%3}, {%4,%5,%6,%7}, {%8,%9}, {%0,%1,%2,%3};" \
        : "+f"((c)[0]), "+f"((c)[1]), "+f"((c)[2]), "+f"((c)[3]) \
        : "r"((a)[0]), "r"((a)[1]), "r"((a)[2]), "r"((a)[3]), "r"((b)[0]), "r"((b)[1]))

// ---------------------------------------------------------------------------
// elementwise tf32 rounding (pre-conversion of GEMM inputs)
// ---------------------------------------------------------------------------
__global__ __launch_bounds__(256) void cvt_tf32_kernel(
    const float4* __restrict__ in, float4* __restrict__ out, int n4)
{
    int i = blockIdx.x * 256 + threadIdx.x;
    if (i < n4) {
        float4 f = in[i];
        float4 o = { f2tf32f(f.x), f2tf32f(f.y), f2tf32f(f.z), f2tf32f(f.w) };
        out[i] = o;
    }
}

// ---------------------------------------------------------------------------
// tf32 warp-MMA GEMM: C[M][Ncols] = A[M,K] * B[Ncols,K]^T + bias[Ncols]
// A, B must already be tf32-rounded. No cvt in the mainloop.
// ---------------------------------------------------------------------------
#define BM 128
#define BN 128
#define ASTR 36
#define STG_BYTES (128*ASTR*4)
#define SM_GEMM (4*STG_BYTES)

__global__ __launch_bounds__(256, 2) void gemm_mma(
    const float* __restrict__ A, const float* __restrict__ B,
    const float* __restrict__ bias, float* __restrict__ C,
    int K, int Ncols)
{
    extern __shared__ float sm[];
    const uint32_t sb = smem_u32(sm);

    const int t = threadIdx.x;
    const int lane = t & 31, wid = t >> 5;
    const int g = lane >> 2, tg = lane & 3;
    const int wm = wid >> 2, wn = wid & 3;
    const int m0 = blockIdx.y * BM, n0 = blockIdx.x * BN;

    const int ldr = t >> 3;
    const int ldc = t & 7;

    float acc[4][4][4];
    #pragma unroll
    for (int i = 0; i < 4; i++)
        #pragma unroll
        for (int j = 0; j < 4; j++)
            #pragma unroll
            for (int r = 0; r < 4; r++) acc[i][j][r] = 0.f;

    const int nch = K >> 5;

    auto issue = [&](int ch, int buf) {
        const float* Ac = A + (size_t)m0 * K + ch * 32;
        const float* Bc = B + (size_t)n0 * K + ch * 32;
        uint32_t dA = sb + buf * STG_BYTES;
        uint32_t dB = sb + 2 * STG_BYTES + buf * STG_BYTES;
        #pragma unroll
        for (int i = 0; i < 4; i++) {
            int row = ldr + i * 32;
            CP16(dA + row * (ASTR * 4) + ldc * 16, Ac + (size_t)row * K + ldc * 4);
        }
        #pragma unroll
        for (int i = 0; i < 4; i++) {
            int row = ldr + i * 32;
            CP16(dB + row * (ASTR * 4) + ldc * 16, Bc + (size_t)row * K + ldc * 4);
        }
        CP_COMMIT();
    };

    issue(0, 0);

    for (int ch = 0; ch < nch; ch++) {
        const int buf = ch & 1;
        if (ch + 1 < nch) { issue(ch + 1, buf ^ 1); CP_WAIT(1); }
        else              { CP_WAIT(0); }
        __syncthreads();

        const float* Ab = sm + buf * (128 * ASTR);
        const float* Bb = sm + 2 * (128 * ASTR) + buf * (128 * ASTR);

        #pragma unroll
        for (int kk = 0; kk < 4; kk++) {
            uint32_t af[4][4], bf[4][2];
            #pragma unroll
            for (int mt = 0; mt < 4; mt++) {
                const float* p = Ab + (wm * 64 + mt * 16 + g) * ASTR + kk * 8 + tg;
                af[mt][0] = __float_as_uint(p[0]);
                af[mt][1] = __float_as_uint(p[8 * ASTR]);
                af[mt][2] = __float_as_uint(p[4]);
                af[mt][3] = __float_as_uint(p[8 * ASTR + 4]);
            }
            #pragma unroll
            for (int nt = 0; nt < 4; nt++) {
                const float* p = Bb + (wn * 32 + nt * 8 + g) * ASTR + kk * 8 + tg;
                bf[nt][0] = __float_as_uint(p[0]);
                bf[nt][1] = __float_as_uint(p[4]);
            }
            #pragma unroll
            for (int mt = 0; mt < 4; mt++)
                #pragma unroll
                for (int nt = 0; nt < 4; nt++)
                    MMA_TF32(acc[mt][nt], af[mt], bf[nt]);
        }
        __syncthreads();
    }

    float bb[4][2];
    #pragma unroll
    for (int nt = 0; nt < 4; nt++) {
        int c = n0 + wn * 32 + nt * 8 + 2 * tg;
        bb[nt][0] = __ldg(bias + c);
        bb[nt][1] = __ldg(bias + c + 1);
    }
    #pragma unroll
    for (int mt = 0; mt < 4; mt++) {
        int r = m0 + wm * 64 + mt * 16 + g;
        #pragma unroll
        for (int nt = 0; nt < 4; nt++) {
            int c = n0 + wn * 32 + nt * 8 + 2 * tg;
            float2 v0 = { acc[mt][nt][0] + bb[nt][0], acc[mt][nt][1] + bb[nt][1] };
            float2 v1 = { acc[mt][nt][2] + bb[nt][0], acc[mt][nt][3] + bb[nt][1] };
            *(float2*)(C + (size_t)r * Ncols + c) = v0;
            *(float2*)(C + (size_t)(r + 8) * Ncols + c) = v1;
        }
    }
}

// ---------------------------------------------------------------------------
// Tensor-core neighborhood attention.
// Block = (head, 8x8 pixel tile). 256 threads = 8 warps.
//   S[64,208] = Q[64,64] * Kw[208,64]^T, masked softmax, O = W * V.
// Staging fully coalesced; V transposed via smem bounce (Vtmp overlays Ws).
// Vtmp stores are SCALAR (stride 65 is not 16B-aligned — float4 would trap).
// ---------------------------------------------------------------------------
#define WIN 14
#define NWIN 196
#define NPAD 208
#define QSTR 68
#define WSTR 212
#define VTSTR 65

#define OFF_Q  0
#define OFF_K  (OFF_Q + 64*QSTR)            // 4352
#define OFF_V  (OFF_K + NPAD*QSTR)          // 18496
#define OFF_W  (OFF_V + 64*WSTR)            // 32064  (also Vtmp[196][65] = 12740 fl)
#define OFF_I  (OFF_W + 64*WSTR)            // 45632
#define SM_NATT ((OFF_I + 64) * 4)          // 182784 B

__global__ __launch_bounds__(256) void natt_mma(
    const float* __restrict__ qkv, float* __restrict__ out)
{
    extern __shared__ float sm[];
    float* Qs = sm + OFF_Q;
    float* Kw = sm + OFF_K;
    float* Vt = sm + OFF_V;
    float* Ws = sm + OFF_W;
    float* Vtmp = sm + OFF_W;               // overlays Ws (dead until QK epilogue)
    float* invs = sm + OFF_I;

    const int tile = blockIdx.x;
    const int h = blockIdx.y;
    const int b = blockIdx.z;
    const int ti0 = (tile / 6) * 8;
    const int tj0 = (tile % 6) * 8;
    const int wr0 = min(max(ti0 - 3, 0), HH - WIN);
    const int wc0 = min(max(tj0 - 3, 0), WW - WIN);

    const int t = threadIdx.x;
    const int lane = t & 31, wid = t >> 5;
    const int g = lane >> 2, tg = lane & 3;
    const float* base = qkv + (size_t)b * HH * WW * QKV_M;

    // ---- stage Q (scaled + tf32), coalesced: 16 lanes cover one pixel row
    #pragma unroll
    for (int v = t; v < 64 * 16; v += 256) {
        int pix = v >> 4, dc = v & 15;
        int gi = ti0 + (pix >> 3), gj = tj0 + (pix & 7);
        float4 f = *(const float4*)(base + ((size_t)gi * WW + gj) * QKV_M + h * HD + dc * 4);
        uint4 u = { f2tf32(f.x * 0.125f), f2tf32(f.y * 0.125f),
                    f2tf32(f.z * 0.125f), f2tf32(f.w * 0.125f) };
        *(uint4*)(Qs + pix * QSTR + dc * 4) = u;
    }
    // ---- stage K (tf32, [wpix][68]) + raw V bounce into Vtmp[wpix][65], coalesced LDG
    for (int v = t; v < NWIN * 16; v += 256) {
        int wpix = v >> 4, dc = v & 15;
        int wr = wr0 + wpix / WIN, wc = wc0 + wpix % WIN;
        const float* p = base + ((size_t)wr * WW + wc) * QKV_M + CC + h * HD + dc * 4;
        float4 kf = *(const float4*)p;
        float4 vf = *(const float4*)(p + CC);
        uint4 u = { f2tf32(kf.x), f2tf32(kf.y), f2tf32(kf.z), f2tf32(kf.w) };
        *(uint4*)(Kw + wpix * QSTR + dc * 4) = u;
        float* vp = Vtmp + wpix * VTSTR + dc * 4;   // odd stride: scalar stores only
        vp[0] = vf.x; vp[1] = vf.y; vp[2] = vf.z; vp[3] = vf.w;
    }
    // zero Vt pad columns 196..211
    #pragma unroll
    for (int v = t; v < 64 * 16; v += 256) {
        Vt[(v >> 4) * WSTR + NWIN + (v & 15)] = 0.f;
    }
    __syncthreads();

    // ---- transpose Vtmp[pix][d] -> Vt[d][pix] (+tf32). Both sides conflict-free.
    for (int u = t; u < 64 * NWIN; u += 256) {
        int d = u / NWIN, pix = u - d * NWIN;
        Vt[d * WSTR + pix] = f2tf32f(Vtmp[pix * VTSTR + d]);
    }
    __syncthreads();

    // ---- QK^T: warp (wm 0..3, wn 0..1); 16 rows x 104 cols per warp
    {
        const int wm = wid >> 1, wn = wid & 1;
        float acc[13][4];
        #pragma unroll
        for (int nt = 0; nt < 13; nt++)
            #pragma unroll
            for (int r = 0; r < 4; r++) acc[nt][r] = 0.f;

        const float* q0 = Qs + (wm * 16 + g) * QSTR + tg;
        const float* q1 = q0 + 8 * QSTR;
        const float* kb = Kw + (wn * 104 + g) * QSTR + tg;

        #pragma unroll
        for (int k = 0; k < 8; k++) {
            uint32_t af[4];
            af[0] = __float_as_uint(q0[k * 8]);
            af[1] = __float_as_uint(q1[k * 8]);
            af[2] = __float_as_uint(q0[k * 8 + 4]);
            af[3] = __float_as_uint(q1[k * 8 + 4]);
            #pragma unroll
            for (int nt = 0; nt < 13; nt++) {
                uint32_t bf[2];
                const float* p = kb + nt * 8 * QSTR + k * 8;
                bf[0] = __float_as_uint(p[0]);
                bf[1] = __float_as_uint(p[4]);
                MMA_TF32(acc[nt], af, bf);
            }
        }
        __syncthreads();   // Vtmp fully consumed; safe to overwrite with Ws
        #pragma unroll
        for (int nt = 0; nt < 13; nt++) {
            int r = wm * 16 + g;
            int n = wn * 104 + nt * 8 + 2 * tg;
            *(float2*)(Ws + r * WSTR + n) = make_float2(acc[nt][0], acc[nt][1]);
            *(float2*)(Ws + (r + 8) * WSTR + n) = make_float2(acc[nt][2], acc[nt][3]);
        }
    }
    __syncthreads();

    // ---- masked softmax (unnormalized); 4 threads per pixel
    {
        const int pix = t >> 2, sub = t & 3;
        const int gi = ti0 + (pix >> 3), gj = tj0 + (pix & 7);
        const int ro = min(max(gi - 3, 0), HH - KK) - wr0;
        const int co = min(max(gj - 3, 0), WW - KK) - wc0;
        float* wrow = Ws + pix * WSTR;

        float mx = -1e30f;
        #pragma unroll 4
        for (int i = 0; i < 52; i++) {
            int n = sub + 4 * i;
            if (n < NWIN) {
                int wr = n / WIN, wc = n - wr * WIN;
                if ((unsigned)(wr - ro) < 7u && (unsigned)(wc - co) < 7u)
                    mx = fmaxf(mx, wrow[n]);
            }
        }
        mx = fmaxf(mx, __shfl_xor_sync(0xffffffffu, mx, 1));
        mx = fmaxf(mx, __shfl_xor_sync(0xffffffffu, mx, 2));

        float lsum = 0.f;
        #pragma unroll 4
        for (int i = 0; i < 52; i++) {
            int n = sub + 4 * i;
            float w = 0.f;
            if (n < NWIN) {
                int wr = n / WIN, wc = n - wr * WIN;
                if ((unsigned)(wr - ro) < 7u && (unsigned)(wc - co) < 7u)
                    w = __expf(wrow[n] - mx);
            }
            wrow[n] = f2tf32f(w);
            lsum += w;
        }
        lsum += __shfl_xor_sync(0xffffffffu, lsum, 1);
        lsum += __shfl_xor_sync(0xffffffffu, lsum, 2);
        if (sub == 0) invs[pix] = 1.f / lsum;
    }
    __syncthreads();

    // ---- O = W * V : warp (wm 0..3, wn 0..1); 16 rows x 32 cols per warp
    {
        const int wm = wid >> 1, wn = wid & 1;
        float acc[4][4];
        #pragma unroll
        for (int nt = 0; nt < 4; nt++)
            #pragma unroll
            for (int r = 0; r < 4; r++) acc[nt][r] = 0.f;

        const float* w0 = Ws + (wm * 16 + g) * WSTR + tg;
        const float* w1 = w0 + 8 * WSTR;
        const float* vb = Vt + (wn * 32 + g) * WSTR + tg;

        #pragma unroll 2
        for (int kb = 0; kb < 26; kb++) {
            uint32_t af[4];
            af[0] = __float_as_uint(w0[kb * 8]);
            af[1] = __float_as_uint(w1[kb * 8]);
            af[2] = __float_as_uint(w0[kb * 8 + 4]);
            af[3] = __float_as_uint(w1[kb * 8 + 4]);
            #pragma unroll
            for (int nt = 0; nt < 4; nt++) {
                uint32_t bf[2];
                const float* p = vb + nt * 8 * WSTR + kb * 8;
                bf[0] = __float_as_uint(p[0]);
                bf[1] = __float_as_uint(p[4]);
                MMA_TF32(acc[nt], af, bf);
            }
        }

        const int r = wm * 16 + g;
        const float inv0 = invs[r], inv1 = invs[r + 8];
        const int gi0 = ti0 + (r >> 3), gj0 = tj0 + (r & 7);
        const int r1 = r + 8;
        const int gi1 = ti0 + (r1 >> 3), gj1 = tj0 + (r1 & 7);
        float* o0 = out + ((size_t)b * HH * WW + (size_t)gi0 * WW + gj0) * CC + h * HD;
        float* o1 = out + ((size_t)b * HH * WW + (size_t)gi1 * WW + gj1) * CC + h * HD;
        // outputs tf32-rounded: this buffer is the A operand of the proj GEMM
        #pragma unroll
        for (int nt = 0; nt < 4; nt++) {
            int c = wn * 32 + nt * 8 + 2 * tg;
            *(float2*)(o0 + c) = make_float2(f2tf32f(acc[nt][0] * inv0), f2tf32f(acc[nt][1] * inv0));
            *(float2*)(o1 + c) = make_float2(f2tf32f(acc[nt][2] * inv1), f2tf32f(acc[nt][3] * inv1));
        }
    }
}

// ---------------------------------------------------------------------------
extern "C" void kernel_launch(void* const* d_in, const int* in_sizes, int n_in,
                              void* d_out, int out_size)
{
    (void)in_sizes; (void)n_in; (void)out_size;
    const float* x      = (const float*)d_in[0];
    const float* qkv_w  = (const float*)d_in[1];
    const float* qkv_b  = (const float*)d_in[2];
    const float* proj_w = (const float*)d_in[3];
    const float* proj_b = (const float*)d_in[4];
    float* out = (float*)d_out;

    float *qkv_s, *att_s, *x_s, *w1_s, *w2_s;
    cudaGetSymbolAddress((void**)&qkv_s, g_qkv);
    cudaGetSymbolAddress((void**)&att_s, g_att);
    cudaGetSymbolAddress((void**)&x_s,   g_x);
    cudaGetSymbolAddress((void**)&w1_s,  g_w1);
    cudaGetSymbolAddress((void**)&w2_s,  g_w2);

    cudaFuncSetAttribute(gemm_mma, cudaFuncAttributeMaxDynamicSharedMemorySize, SM_GEMM);
    cudaFuncSetAttribute(natt_mma, cudaFuncAttributeMaxDynamicSharedMemorySize, SM_NATT);

    // 0) pre-round GEMM inputs to tf32 (rna)
    {
        int n4x = NPIX * CC / 4;            // 589824
        int n4w1 = QKV_M * CC / 4;          // 196608
        int n4w2 = CC * CC / 4;             // 65536
        cvt_tf32_kernel<<<(n4x + 255) / 256, 256>>>((const float4*)x, (float4*)x_s, n4x);
        cvt_tf32_kernel<<<(n4w1 + 255) / 256, 256>>>((const float4*)qkv_w, (float4*)w1_s, n4w1);
        cvt_tf32_kernel<<<(n4w2 + 255) / 256, 256>>>((const float4*)proj_w, (float4*)w2_s, n4w2);
    }
    // 1) QKV projection (tf32 HMMA, pre-rounded inputs)
    {
        dim3 grid(QKV_M / BN, NPIX / BM);     // (12, 36)
        gemm_mma<<<grid, 256, SM_GEMM>>>(x_s, w1_s, qkv_b, qkv_s, CC, QKV_M);
    }
    // 2) neighborhood attention (tf32 HMMA)
    {
        dim3 grid(36, NH, BATCH);
        natt_mma<<<grid, 256, SM_NATT>>>(qkv_s, att_s);
    }
    // 3) output projection
    {
        dim3 grid(CC / BN, NPIX / BM);        // (4, 36)
        gemm_mma<<<grid, 256, SM_GEMM>>>(att_s, w2_s, proj_b, out, CC, CC);
    }
}